// round 4
// baseline (speedup 1.0000x reference)
#include <cuda_runtime.h>
#include <math.h>

#define MAXN 8192
#define NKEY 128            // NUM_IMGS(8) * NUM_CLASSES(16)
#define NUM_CLASSES 16
#define NB 128              // blocks (<=148 SMs -> all co-resident, spin-barrier safe)
#define NT 256              // threads per block

// ---- scratch (no allocations; all state self-resetting per call) ----
__device__ float4 g_ua[MAXN];          // unsorted packed {cx, cy, inv, score}
__device__ float2 g_uv[MAXN];          // unsorted {cos4t, sin4t}
__device__ int    g_ukey[MAXN];
__device__ float4 s_a[MAXN];           // key-sorted
__device__ float2 s_v[MAXN];
__device__ int    s_key[MAXN];
__device__ int    g_hist[NKEY];        // zero at load; re-zeroed by scan each call
__device__ int    g_offs[NKEY + 1];
__device__ int    g_cursor[NKEY];
__device__ volatile int g_bar[3];      // grid-barrier counters (self-resetting)
__device__ int    g_done;              // finish ticket

// grid barrier: whole block arrives; thread 0 spins; resets previous barrier
__device__ __forceinline__ void gbar(int id) {
    __syncthreads();
    __threadfence();                       // release: phase writes visible
    if (threadIdx.x == 0) {
        atomicAdd((int*)&g_bar[id], 1);
        while (g_bar[id] < NB) { }
        if (id > 0) g_bar[id - 1] = 0;     // all blocks passed id-1 -> safe reset
    }
    __syncthreads();
    __threadfence();                       // acquire
}

__global__ __launch_bounds__(NT)
void k_fused(const float* __restrict__ preds,
             const float* __restrict__ scores,
             const int*   __restrict__ labels,
             const int*   __restrict__ batch,
             float* __restrict__ out, int n, float inv_n) {
    const int tid  = blockIdx.x * NT + threadIdx.x;
    const int lane = threadIdx.x & 31;
    const int wib  = threadIdx.x >> 5;               // warp in block

    // ---- P1: per-point precompute + key histogram ----
    if (tid == 0) *out = 0.0f;
    if (tid < n) {
        const float* p = preds + 5 * tid;
        float cx = p[0], cy = p[1], w = p[2], h = p[3], th = p[4];
        float scale = fminf(fmaxf(sqrtf(w * h), 16.0f), 800.0f);
        float sig = 2.0f * scale;                    // K_RADIUS = 2
        float inv = 1.0f / (2.0f * sig * sig);
        float sn, cs;
        sincosf(4.0f * th, &sn, &cs);
        g_ua[tid] = make_float4(cx, cy, inv, scores[tid]); // SCORE_ALPHA = 1
        g_uv[tid] = make_float2(cs, sn);
        int key = batch[tid] * NUM_CLASSES + labels[tid];
        g_ukey[tid] = key;
        atomicAdd(&g_hist[key], 1);
    }
    gbar(0);

    // ---- P2: 128-bin exclusive scan (block 0, warp 0) + hist reset ----
    if (blockIdx.x == 0 && threadIdx.x < 32) {
        int l = threadIdx.x;                          // lane owns bins 4l..4l+3
        int v0 = g_hist[4 * l],     v1 = g_hist[4 * l + 1];
        int v2 = g_hist[4 * l + 2], v3 = g_hist[4 * l + 3];
        int s = v0 + v1 + v2 + v3;
        int incl = s;
        #pragma unroll
        for (int o = 1; o < 32; o <<= 1) {
            int x = __shfl_up_sync(0xffffffffu, incl, o);
            if (l >= o) incl += x;
        }
        int e = incl - s;                             // exclusive prefix
        g_offs[4 * l] = e;                 g_cursor[4 * l] = e;
        g_offs[4 * l + 1] = e + v0;        g_cursor[4 * l + 1] = e + v0;
        g_offs[4 * l + 2] = e + v0 + v1;   g_cursor[4 * l + 2] = e + v0 + v1;
        g_offs[4 * l + 3] = e + v0 + v1 + v2;
        g_cursor[4 * l + 3] = e + v0 + v1 + v2;
        if (l == 31) g_offs[NKEY] = incl;
        g_hist[4 * l] = 0; g_hist[4 * l + 1] = 0;     // reset for next call
        g_hist[4 * l + 2] = 0; g_hist[4 * l + 3] = 0;
    }
    gbar(1);

    // ---- P3: scatter into key-sorted SoA ----
    if (tid < n) {
        int key = g_ukey[tid];
        int p = atomicAdd(&g_cursor[key], 1);
        s_a[p] = g_ua[tid];
        s_v[p] = g_uv[tid];
        s_key[p] = key;
    }
    gbar(2);

    // ---- P4: warp-per-point sweep; each warp owns 8 consecutive sorted points ----
    float chaos_sum = 0.0f;                           // lane 0 accumulates
    int wid = blockIdx.x * (NT / 32) + wib;           // global warp id
    int pbase = wid * 8;
    #pragma unroll
    for (int k = 0; k < 8; ++k) {
        int p = pbase + k;
        if (p >= n) break;
        float4 a = s_a[p];                            // broadcast (uniform addr)
        int key = s_key[p];
        int beg = g_offs[key], end = g_offs[key + 1];
        float den = 0.0f, nx = 0.0f, ny = 0.0f;
        for (int j = beg + lane; j < end; j += 32) {
            float4 b = s_a[j];
            float2 v = s_v[j];
            float dx = a.x - b.x;
            float dy = a.y - b.y;
            float wgt = __expf(-(dx * dx + dy * dy) * a.z) * b.w;
            den += wgt;
            nx  += wgt * v.x;
            ny  += wgt * v.y;
        }
        #pragma unroll
        for (int o = 16; o; o >>= 1) {
            den += __shfl_xor_sync(0xffffffffu, den, o);
            nx  += __shfl_xor_sync(0xffffffffu, nx, o);
            ny  += __shfl_xor_sync(0xffffffffu, ny, o);
        }
        if (lane == 0) chaos_sum += 1.0f - sqrtf(nx * nx + ny * ny) / den;
    }

    // ---- block reduce + one atomicAdd per block ----
    __shared__ float red[NT / 32];
    if (lane == 0) red[wib] = chaos_sum;
    __syncthreads();
    if (threadIdx.x < NT / 32) {
        float v = red[threadIdx.x];
        v += __shfl_xor_sync(0xffu, v, 4);
        v += __shfl_xor_sync(0xffu, v, 2);
        v += __shfl_xor_sync(0xffu, v, 1);
        if (threadIdx.x == 0) atomicAdd(out, v * inv_n);   // LOSS_WEIGHT = 1
    }

    // finish ticket: last block resets bar[2] and ticket for next replay
    __syncthreads();
    if (threadIdx.x == 0) {
        __threadfence();
        int t = atomicAdd(&g_done, 1);
        if (t == NB - 1) { g_bar[2] = 0; g_done = 0; }
    }
}

extern "C" void kernel_launch(void* const* d_in, const int* in_sizes, int n_in,
                              void* d_out, int out_size) {
    const float* preds  = (const float*)d_in[0];
    const float* scores = (const float*)d_in[1];
    const int*   labels = (const int*)d_in[2];
    const int*   batch  = (const int*)d_in[3];
    float* out = (float*)d_out;
    int n = in_sizes[1];                 // pos_scores element count = N

    k_fused<<<NB, NT>>>(preds, scores, labels, batch, out, n, 1.0f / (float)n);
}